// round 13
// baseline (speedup 1.0000x reference)
#include <cuda_runtime.h>
#include <cuda_fp16.h>
#include <cstdint>

// Problem constants
#define NB     2
#define CIN    256
#define NTOK   4096
#define NH     8
#define DH     64
#define CINNER 512         // NH*DH
#define CQKV   1536        // 3*CINNER
#define NKT    (NTOK / 64) // 64 key tiles

// Scratch (allocation-free rule: __device__ globals)
__device__ float g_qkv[NB * CQKV * NTOK];            // [B][1536][N]
__device__ float g_norms[2 * NB * NH * NTOK];        // q2,k2 PRE-SCALED by LOG2E^2
__device__ float g_ao[NB * CINNER * NTOK];           // attention output [B][512][N]
// fp16 fragment-ordered K/V, lane-contiguous for LDS.128:
//   K word idx = nt*128 + lane*4 + ks
//   V word idx = ntp*256 + lane*8 + ddnt
__device__ uint2 g_kf[NB * NH * NKT * 1024];
__device__ uint2 g_vf[NB * NH * NKT * 1024];

// ---------------------------------------------------------------------------
// helpers
// ---------------------------------------------------------------------------
__device__ __forceinline__ void mma16(float c[4], const uint32_t a[4],
                                      uint32_t b0, uint32_t b1) {
    asm volatile(
        "mma.sync.aligned.m16n8k16.row.col.f32.f16.f16.f32 "
        "{%0,%1,%2,%3}, {%4,%5,%6,%7}, {%8,%9}, {%0,%1,%2,%3};"
        : "+f"(c[0]), "+f"(c[1]), "+f"(c[2]), "+f"(c[3])
        : "r"(a[0]), "r"(a[1]), "r"(a[2]), "r"(a[3]), "r"(b0), "r"(b1));
}

__device__ __forceinline__ uint32_t packh2(float lo, float hi) {
    __half2 h = __floats2half2_rn(lo, hi);   // .x = lo (low 16 bits)
    return *(uint32_t*)&h;
}

__device__ __forceinline__ uint2 split2(float e0, float e1) {
    __half h0 = __float2half_rn(e0);
    __half h1 = __float2half_rn(e1);
    float l0 = e0 - __half2float(h0);
    float l1 = e1 - __half2float(h1);
    __half2 hh = __halves2half2(h0, h1);
    __half2 ll = __floats2half2_rn(l0, l1);
    return make_uint2(*(uint32_t*)&hh, *(uint32_t*)&ll);
}

__device__ __forceinline__ uint32_t smem_u32(const void* p) {
    uint32_t a;
    asm("{ .reg .u64 t; cvta.to.shared.u64 t, %1; cvt.u32.u64 %0, t; }"
        : "=r"(a) : "l"(p));
    return a;
}

__device__ __forceinline__ void cp16(uint32_t dst, const void* src) {
    asm volatile("cp.async.cg.shared.global [%0], [%1], 16;"
                 :: "r"(dst), "l"(src) : "memory");
}
#define CP_COMMIT() asm volatile("cp.async.commit_group;" ::: "memory")
#define CP_WAIT(n)  asm volatile("cp.async.wait_group %0;" :: "n"(n) : "memory")

// ---------------------------------------------------------------------------
// 3xfp16 (hi/lo split) tensor-core GEMM (R8/R9 version — best known)
// ---------------------------------------------------------------------------
__global__ void __launch_bounds__(256, 2) gemm_tc_kernel(
    const float* __restrict__ W, const float* __restrict__ X, float* __restrict__ Y,
    int K, long xStride, long yStride)
{
    extern __shared__ uint2 sm2[];
    uint2* XS = sm2;              // 16 x 72
    uint2* WS = sm2 + 16 * 72;    // 16 x 136

    const int tid = threadIdx.x;
    const int lane = tid & 31, w = tid >> 5;
    const int quad = lane & 3, g = lane >> 2;
    const int wn = w >> 2, wo = w & 3;
    const int nblk = blockIdx.x * 64;
    const int oblk = blockIdx.y * 128;
    const float* Xb = X + (long)blockIdx.z * xStride;
    float*       Yb = Y + (long)blockIdx.z * yStride;

    const int xrp = tid >> 4;
    const int xn4 = (tid & 15) << 2;
    const int wor = tid >> 1;
    const int wch = tid & 1;
    const float* xsrc = Xb + (long)(2 * xrp) * NTOK + nblk + xn4;
    const float* wsrc = W + (long)(oblk + wor) * K + wch * 16;

    float acc[2][4][4];
    #pragma unroll
    for (int mt = 0; mt < 2; mt++)
        #pragma unroll
        for (int ot = 0; ot < 4; ot++)
            #pragma unroll
            for (int r = 0; r < 4; r++) acc[mt][ot][r] = 0.f;

    float4 xr0 = *(const float4*)(xsrc);
    float4 xr1 = *(const float4*)(xsrc + NTOK);
    float4 wr0 = *(const float4*)(wsrc);
    float4 wr1 = *(const float4*)(wsrc + 4);
    float4 wr2 = *(const float4*)(wsrc + 8);
    float4 wr3 = *(const float4*)(wsrc + 12);

    for (int kc = 0; kc < K; kc += 32) {
        __syncthreads();
        {
            float ea[4] = {xr0.x, xr0.y, xr0.z, xr0.w};
            float eb[4] = {xr1.x, xr1.y, xr1.z, xr1.w};
            #pragma unroll
            for (int e = 0; e < 4; e++)
                XS[xrp * 72 + xn4 + e] = split2(ea[e], eb[e]);
        }
        {
            float vv[16] = {wr0.x, wr0.y, wr0.z, wr0.w, wr1.x, wr1.y, wr1.z, wr1.w,
                            wr2.x, wr2.y, wr2.z, wr2.w, wr3.x, wr3.y, wr3.z, wr3.w};
            #pragma unroll
            for (int p = 0; p < 8; p++)
                WS[(8 * wch + p) * 136 + wor] = split2(vv[2 * p], vv[2 * p + 1]);
        }
        __syncthreads();

        if (kc + 32 < K) {
            const float* xs = xsrc + (long)(kc + 32) * NTOK;
            const float* ws = wsrc + kc + 32;
            xr0 = *(const float4*)(xs);
            xr1 = *(const float4*)(xs + NTOK);
            wr0 = *(const float4*)(ws);
            wr1 = *(const float4*)(ws + 4);
            wr2 = *(const float4*)(ws + 8);
            wr3 = *(const float4*)(ws + 12);
        }

        #pragma unroll
        for (int s = 0; s < 2; s++) {
            const int cpa = 8 * s + quad;
            uint32_t ah[2][4], al[2][4];
            #pragma unroll
            for (int mt = 0; mt < 2; mt++) {
                int n = 32 * wn + 16 * mt + g;
                uint2 w0 = XS[cpa * 72 + n];
                uint2 w1 = XS[cpa * 72 + n + 8];
                uint2 w2 = XS[(cpa + 4) * 72 + n];
                uint2 w3 = XS[(cpa + 4) * 72 + n + 8];
                ah[mt][0] = w0.x; al[mt][0] = w0.y;
                ah[mt][1] = w1.x; al[mt][1] = w1.y;
                ah[mt][2] = w2.x; al[mt][2] = w2.y;
                ah[mt][3] = w3.x; al[mt][3] = w3.y;
            }
            #pragma unroll
            for (int ot = 0; ot < 4; ot++) {
                int o = 32 * wo + 8 * ot + g;
                uint2 b0 = WS[cpa * 136 + o];
                uint2 b1 = WS[(cpa + 4) * 136 + o];
                #pragma unroll
                for (int mt = 0; mt < 2; mt++) {
                    mma16(acc[mt][ot], al[mt], b0.x, b1.x);
                    mma16(acc[mt][ot], ah[mt], b0.y, b1.y);
                    mma16(acc[mt][ot], ah[mt], b0.x, b1.x);
                }
            }
        }
    }

    #pragma unroll
    for (int mt = 0; mt < 2; mt++)
        #pragma unroll
        for (int ot = 0; ot < 4; ot++) {
            int n = nblk + 32 * wn + 16 * mt + g;
            int o = oblk + 32 * wo + 8 * ot + 2 * quad;
            Yb[(long)o * NTOK + n]           = acc[mt][ot][0];
            Yb[(long)(o + 1) * NTOK + n]     = acc[mt][ot][1];
            Yb[(long)o * NTOK + n + 8]       = acc[mt][ot][2];
            Yb[(long)(o + 1) * NTOK + n + 8] = acc[mt][ot][3];
        }
}

// ---------------------------------------------------------------------------
// Norms: q2/k2 pre-scaled by LOG2E^2 (only attention consumes these)
// ---------------------------------------------------------------------------
__global__ void __launch_bounds__(256) norms_kernel()
{
    constexpr float L2 = 1.4426950408889634f * 1.4426950408889634f;
    int idx = blockIdx.x * 256 + threadIdx.x;
    int n = idx & (NTOK - 1);
    int t = idx >> 12;
    int h = t & 7;
    int pb = t >> 3;
    int part = pb & 1;
    int b = pb >> 1;
    const float* p = g_qkv + ((long)(b * CQKV + part * CINNER + h * DH)) * NTOK + n;
    float s = 0.f;
    #pragma unroll
    for (int d = 0; d < DH; d++) { float v = p[(long)d * NTOK]; s = fmaf(v, v, s); }
    g_norms[(long)part * (NB * NH * NTOK) + (long)(b * NH + h) * NTOK + n] = s * L2;
}

// ---------------------------------------------------------------------------
// K/V fragment pre-conversion, lane-contiguous layouts (LDS.128-friendly):
//   K word idx = nt*128 + lane*4 + ks
//   V word idx = ntp*256 + lane*8 + ddnt
// ---------------------------------------------------------------------------
__global__ void __launch_bounds__(256) frag_kernel()
{
    const int kt = blockIdx.x, bh = blockIdx.y, isV = blockIdx.z;
    const int b = bh >> 3, h = bh & 7;
    const int nk = kt * 64;
    const float* src = g_qkv + (long)(b * CQKV + (isV ? 2 : 1) * CINNER + h * DH) * NTOK;
    uint2* dst = (isV ? g_vf : g_kf) + ((long)bh * NKT + kt) * 1024;

    #pragma unroll
    for (int it = 0; it < 4; it++) {
        int w = threadIdx.x + it * 256;
        uint2 r;
        if (!isV) {
            int nt = w >> 7, rem = w & 127;
            int lane = rem >> 2, ks = rem & 3;
            int quad = lane & 3, g = lane >> 2;
            int d0 = 16 * ks + 2 * quad;
            int j = nk + 8 * nt + g;
            r.x = packh2(src[(long)d0 * NTOK + j],       src[(long)(d0 + 1) * NTOK + j]);
            r.y = packh2(src[(long)(d0 + 8) * NTOK + j], src[(long)(d0 + 9) * NTOK + j]);
        } else {
            int ntp = w >> 8, rem = w & 255;
            int lane = rem >> 3, ddnt = rem & 7;
            int quad = lane & 3, g = lane >> 2;
            int dd = 8 * ddnt + g;
            int key0 = nk + 16 * ntp + 2 * quad;
            float2 v0 = *(const float2*)&src[(long)dd * NTOK + key0];
            float2 v1 = *(const float2*)&src[(long)dd * NTOK + key0 + 8];
            r.x = packh2(v0.x, v0.y);
            r.y = packh2(v1.x, v1.y);
        }
        dst[w] = r;
    }
}

// ---------------------------------------------------------------------------
// Flash distance attention: fp16 m16n8k16, pre-fragmented K/V via cp.async
// double buffering, LDS.128 loads, prescaled softmax, fabs instead of fmax.
// ---------------------------------------------------------------------------
__global__ void __launch_bounds__(256, 2) attn_mma_kernel()
{
    __shared__ uint4 KFs[2][512];    // 2 x 8KB
    __shared__ uint4 VFs[2][512];    // 2 x 8KB
    __shared__ float k2ss[2][64];

    const int tid  = threadIdx.x;
    const int wid  = tid >> 5;
    const int lane = tid & 31;
    const int quad = lane & 3;
    const int g    = lane >> 2;
    const int n0   = blockIdx.x * 128;
    const int h = blockIdx.y, b = blockIdx.z;
    const int bh = b * NH + h;

    const float* qb  = g_qkv + (long)(b * CQKV + h * DH) * NTOK;
    const float* k2g = g_norms + (long)NB * NH * NTOK + (long)bh * NTOK;
    const uint4* kfg = (const uint4*)(g_kf + (long)bh * NKT * 1024);
    const uint4* vfg = (const uint4*)(g_vf + (long)bh * NKT * 1024);

    const uint32_t kfS = smem_u32(KFs);
    const uint32_t vfS = smem_u32(VFs);
    const uint32_t k2S = smem_u32(k2ss);

    const int i0 = n0 + wid * 16 + g;

    // Q A-fragments (fp16)
    uint32_t aq[4][4];
    #pragma unroll
    for (int ks = 0; ks < 4; ks++) {
        int d0 = 16 * ks + 2 * quad;
        aq[ks][0] = packh2(qb[(long)d0 * NTOK + i0],       qb[(long)(d0 + 1) * NTOK + i0]);
        aq[ks][1] = packh2(qb[(long)d0 * NTOK + i0 + 8],   qb[(long)(d0 + 1) * NTOK + i0 + 8]);
        aq[ks][2] = packh2(qb[(long)(d0 + 8) * NTOK + i0], qb[(long)(d0 + 9) * NTOK + i0]);
        aq[ks][3] = packh2(qb[(long)(d0 + 8) * NTOK + i0 + 8],
                           qb[(long)(d0 + 9) * NTOK + i0 + 8]);
    }
    const float q2a = g_norms[(long)bh * NTOK + i0];        // pre-scaled
    const float q2b = g_norms[(long)bh * NTOK + i0 + 8];    // pre-scaled

    constexpr float LOG2E  = 1.4426950408889634f;
    constexpr float NSHIFT = -12.0f * LOG2E;
    constexpr float M2L    = -2.0f * LOG2E * LOG2E;

    float o[8][4];
    #pragma unroll
    for (int nt = 0; nt < 8; nt++)
        #pragma unroll
        for (int r = 0; r < 4; r++) o[nt][r] = 0.f;
    float lsum0 = 0.f, lsum1 = 0.f;

    auto stage = [&](int kt, int buf) {
        const uint4* ks_ = kfg + (long)kt * 512;
        const uint4* vs_ = vfg + (long)kt * 512;
        uint32_t kd = kfS + (uint32_t)buf * 8192u + (uint32_t)tid * 16u;
        uint32_t vd = vfS + (uint32_t)buf * 8192u + (uint32_t)tid * 16u;
        cp16(kd,         ks_ + tid);
        cp16(kd + 4096u, ks_ + 256 + tid);
        cp16(vd,         vs_ + tid);
        cp16(vd + 4096u, vs_ + 256 + tid);
        if (tid < 16)
            cp16(k2S + (uint32_t)buf * 256u + (uint32_t)tid * 16u,
                 (const float4*)(k2g + kt * 64) + tid);
        CP_COMMIT();
    };

    stage(0, 0);

    for (int kt = 0; kt < NKT; kt++) {
        const int buf = kt & 1;
        CP_WAIT(0);
        __syncthreads();     // tile kt visible; all warps done with buf^1
        if (kt + 1 < NKT) stage(kt + 1, buf ^ 1);

        const uint4* KB4 = KFs[buf];
        const uint4* VB4 = VFs[buf];
        const float* k2p = k2ss[buf];

        #pragma unroll
        for (int ntp = 0; ntp < 4; ntp++) {
            float c[2][4];
            #pragma unroll
            for (int sub = 0; sub < 2; sub++) {
                int nt = 2 * ntp + sub;
                c[sub][0] = c[sub][1] = c[sub][2] = c[sub][3] = 0.f;
                const uint4* kfp = KB4 + nt * 64 + lane * 2;
                uint4 kA = kfp[0];
                uint4 kB = kfp[1];
                mma16(c[sub], aq[0], kA.x, kA.y);
                mma16(c[sub], aq[1], kA.z, kA.w);
                mma16(c[sub], aq[2], kB.x, kB.y);
                mma16(c[sub], aq[3], kB.z, kB.w);
            }

            float p[2][4];
            #pragma unroll
            for (int sub = 0; sub < 2; sub++) {
                int nt = 2 * ntp + sub;
                float2 k2c = *(const float2*)&k2p[8 * nt + 2 * quad];
                float a0 = q2a + k2c.x, a1 = q2a + k2c.y;
                float b0_ = q2b + k2c.x, b1_ = q2b + k2c.y;
                float s;
                asm("sqrt.approx.f32 %0, %1;" : "=f"(s)
                    : "f"(fabsf(fmaf(M2L, c[sub][0], a0))));
                asm("ex2.approx.f32 %0, %1;" : "=f"(p[sub][0]) : "f"(s + NSHIFT));
                asm("sqrt.approx.f32 %0, %1;" : "=f"(s)
                    : "f"(fabsf(fmaf(M2L, c[sub][1], a1))));
                asm("ex2.approx.f32 %0, %1;" : "=f"(p[sub][1]) : "f"(s + NSHIFT));
                asm("sqrt.approx.f32 %0, %1;" : "=f"(s)
                    : "f"(fabsf(fmaf(M2L, c[sub][2], b0_))));
                asm("ex2.approx.f32 %0, %1;" : "=f"(p[sub][2]) : "f"(s + NSHIFT));
                asm("sqrt.approx.f32 %0, %1;" : "=f"(s)
                    : "f"(fabsf(fmaf(M2L, c[sub][3], b1_))));
                asm("ex2.approx.f32 %0, %1;" : "=f"(p[sub][3]) : "f"(s + NSHIFT));
                lsum0 += p[sub][0] + p[sub][1];
                lsum1 += p[sub][2] + p[sub][3];
            }

            uint32_t ap[4];
            ap[0] = packh2(p[0][0], p[0][1]);
            ap[1] = packh2(p[0][2], p[0][3]);
            ap[2] = packh2(p[1][0], p[1][1]);
            ap[3] = packh2(p[1][2], p[1][3]);

            const uint4* vfp = VB4 + ntp * 128 + lane * 4;
            uint4 v0 = vfp[0], v1 = vfp[1], v2 = vfp[2], v3 = vfp[3];
            mma16(o[0], ap, v0.x, v0.y); mma16(o[1], ap, v0.z, v0.w);
            mma16(o[2], ap, v1.x, v1.y); mma16(o[3], ap, v1.z, v1.w);
            mma16(o[4], ap, v2.x, v2.y); mma16(o[5], ap, v2.z, v2.w);
            mma16(o[6], ap, v3.x, v3.y); mma16(o[7], ap, v3.z, v3.w);
        }
    }

    lsum0 += __shfl_xor_sync(0xffffffffu, lsum0, 1);
    lsum0 += __shfl_xor_sync(0xffffffffu, lsum0, 2);
    lsum1 += __shfl_xor_sync(0xffffffffu, lsum1, 1);
    lsum1 += __shfl_xor_sync(0xffffffffu, lsum1, 2);
    const float inv0 = 1.f / lsum0;
    const float inv1 = 1.f / lsum1;

    float* aob = g_ao + (long)(b * CINNER + h * DH) * NTOK;
    #pragma unroll
    for (int nt = 0; nt < 8; nt++) {
        int dd = 8 * nt + 2 * quad;
        aob[(long)dd * NTOK + i0]           = o[nt][0] * inv0;
        aob[(long)(dd + 1) * NTOK + i0]     = o[nt][1] * inv0;
        aob[(long)dd * NTOK + i0 + 8]       = o[nt][2] * inv1;
        aob[(long)(dd + 1) * NTOK + i0 + 8] = o[nt][3] * inv1;
    }
}

// ---------------------------------------------------------------------------
extern "C" void kernel_launch(void* const* d_in, const int* in_sizes, int n_in,
                              void* d_out, int out_size)
{
    (void)in_sizes; (void)n_in; (void)out_size;
    const float* fmap  = (const float*)d_in[0];   // [2,256,64,64]
    const float* w_qkv = (const float*)d_in[1];   // [1536,256]
    const float* w_out = (const float*)d_in[2];   // [256,512]
    float* out = (float*)d_out;                   // [2,256,64,64]

    void* qkvPtr = nullptr;
    void* aoPtr  = nullptr;
    cudaGetSymbolAddress(&qkvPtr, g_qkv);
    cudaGetSymbolAddress(&aoPtr,  g_ao);

    const int gemmSmem = (16 * 72 + 16 * 136) * 8;   // 26624 B
    cudaFuncSetAttribute(gemm_tc_kernel,
                         cudaFuncAttributeMaxDynamicSharedMemorySize, gemmSmem);

    // K1: QKV projection (3xfp16 hi/lo)
    {
        dim3 grid(NTOK / 64, CQKV / 128, NB);
        gemm_tc_kernel<<<grid, 256, gemmSmem>>>(w_qkv, fmap, (float*)qkvPtr,
                                                CIN, (long)CIN * NTOK, (long)CQKV * NTOK);
    }
    // K2: norms (pre-scaled by LOG2E^2)
    norms_kernel<<<(NB * NH * 2 * NTOK) / 256, 256>>>();

    // K2.5: K/V fragment pre-conversion (lane-contiguous layout)
    {
        dim3 grid(NKT, NB * NH, 2);
        frag_kernel<<<grid, 256>>>();
    }
    // K3: fp16 attention
    {
        dim3 grid(NTOK / 128, NH, NB);
        attn_mma_kernel<<<grid, 256>>>();
    }
    // K4: output projection (3xfp16 hi/lo)
    {
        dim3 grid(NTOK / 64, CIN / 128, NB);
        gemm_tc_kernel<<<grid, 256, gemmSmem>>>(w_out, (const float*)aoPtr, out,
                                                CINNER, (long)CINNER * NTOK, (long)CIN * NTOK);
    }
}

// round 14
// speedup vs baseline: 1.4398x; 1.4398x over previous
#include <cuda_runtime.h>
#include <cuda_fp16.h>
#include <cstdint>

// Problem constants
#define NB     2
#define CIN    256
#define NTOK   4096
#define NH     8
#define DH     64
#define CINNER 512         // NH*DH
#define CQKV   1536        // 3*CINNER
#define NKT    (NTOK / 64) // 64 key tiles

// Scratch (allocation-free rule: __device__ globals)
__device__ float g_qkv[NB * CQKV * NTOK];            // [B][1536][N]
__device__ float g_norms[2 * NB * NH * NTOK];        // q2,k2 PRE-SCALED by LOG2E^2
__device__ float g_ao[NB * CINNER * NTOK];           // attention output [B][512][N]
// fp16 fragment-ordered K/V (R9 layout): [bh][kt][1024] uint2
//   K word idx: nt*128 + ks*32 + lane
//   V word idx: ntp*256 + ddnt*32 + lane
__device__ uint2 g_kf[NB * NH * NKT * 1024];
__device__ uint2 g_vf[NB * NH * NKT * 1024];

// ---------------------------------------------------------------------------
// helpers
// ---------------------------------------------------------------------------
__device__ __forceinline__ void mma16(float c[4], const uint32_t a[4],
                                      uint32_t b0, uint32_t b1) {
    asm volatile(
        "mma.sync.aligned.m16n8k16.row.col.f32.f16.f16.f32 "
        "{%0,%1,%2,%3}, {%4,%5,%6,%7}, {%8,%9}, {%0,%1,%2,%3};"
        : "+f"(c[0]), "+f"(c[1]), "+f"(c[2]), "+f"(c[3])
        : "r"(a[0]), "r"(a[1]), "r"(a[2]), "r"(a[3]), "r"(b0), "r"(b1));
}

__device__ __forceinline__ uint32_t packh2(float lo, float hi) {
    __half2 h = __floats2half2_rn(lo, hi);   // .x = lo (low 16 bits)
    return *(uint32_t*)&h;
}

__device__ __forceinline__ uint2 split2(float e0, float e1) {
    __half h0 = __float2half_rn(e0);
    __half h1 = __float2half_rn(e1);
    float l0 = e0 - __half2float(h0);
    float l1 = e1 - __half2float(h1);
    __half2 hh = __halves2half2(h0, h1);
    __half2 ll = __floats2half2_rn(l0, l1);
    return make_uint2(*(uint32_t*)&hh, *(uint32_t*)&ll);
}

__device__ __forceinline__ uint32_t smem_u32(const void* p) {
    uint32_t a;
    asm("{ .reg .u64 t; cvta.to.shared.u64 t, %1; cvt.u32.u64 %0, t; }"
        : "=r"(a) : "l"(p));
    return a;
}

__device__ __forceinline__ void cp16(uint32_t dst, const void* src) {
    asm volatile("cp.async.cg.shared.global [%0], [%1], 16;"
                 :: "r"(dst), "l"(src) : "memory");
}
#define CP_COMMIT() asm volatile("cp.async.commit_group;" ::: "memory")
#define CP_WAIT(n)  asm volatile("cp.async.wait_group %0;" :: "n"(n) : "memory")

// ---------------------------------------------------------------------------
// 3xfp16 (hi/lo split) tensor-core GEMM (R8/R9 version — best known)
// ---------------------------------------------------------------------------
__global__ void __launch_bounds__(256, 2) gemm_tc_kernel(
    const float* __restrict__ W, const float* __restrict__ X, float* __restrict__ Y,
    int K, long xStride, long yStride)
{
    extern __shared__ uint2 sm2[];
    uint2* XS = sm2;              // 16 x 72
    uint2* WS = sm2 + 16 * 72;    // 16 x 136

    const int tid = threadIdx.x;
    const int lane = tid & 31, w = tid >> 5;
    const int quad = lane & 3, g = lane >> 2;
    const int wn = w >> 2, wo = w & 3;
    const int nblk = blockIdx.x * 64;
    const int oblk = blockIdx.y * 128;
    const float* Xb = X + (long)blockIdx.z * xStride;
    float*       Yb = Y + (long)blockIdx.z * yStride;

    const int xrp = tid >> 4;
    const int xn4 = (tid & 15) << 2;
    const int wor = tid >> 1;
    const int wch = tid & 1;
    const float* xsrc = Xb + (long)(2 * xrp) * NTOK + nblk + xn4;
    const float* wsrc = W + (long)(oblk + wor) * K + wch * 16;

    float acc[2][4][4];
    #pragma unroll
    for (int mt = 0; mt < 2; mt++)
        #pragma unroll
        for (int ot = 0; ot < 4; ot++)
            #pragma unroll
            for (int r = 0; r < 4; r++) acc[mt][ot][r] = 0.f;

    float4 xr0 = *(const float4*)(xsrc);
    float4 xr1 = *(const float4*)(xsrc + NTOK);
    float4 wr0 = *(const float4*)(wsrc);
    float4 wr1 = *(const float4*)(wsrc + 4);
    float4 wr2 = *(const float4*)(wsrc + 8);
    float4 wr3 = *(const float4*)(wsrc + 12);

    for (int kc = 0; kc < K; kc += 32) {
        __syncthreads();
        {
            float ea[4] = {xr0.x, xr0.y, xr0.z, xr0.w};
            float eb[4] = {xr1.x, xr1.y, xr1.z, xr1.w};
            #pragma unroll
            for (int e = 0; e < 4; e++)
                XS[xrp * 72 + xn4 + e] = split2(ea[e], eb[e]);
        }
        {
            float vv[16] = {wr0.x, wr0.y, wr0.z, wr0.w, wr1.x, wr1.y, wr1.z, wr1.w,
                            wr2.x, wr2.y, wr2.z, wr2.w, wr3.x, wr3.y, wr3.z, wr3.w};
            #pragma unroll
            for (int p = 0; p < 8; p++)
                WS[(8 * wch + p) * 136 + wor] = split2(vv[2 * p], vv[2 * p + 1]);
        }
        __syncthreads();

        if (kc + 32 < K) {
            const float* xs = xsrc + (long)(kc + 32) * NTOK;
            const float* ws = wsrc + kc + 32;
            xr0 = *(const float4*)(xs);
            xr1 = *(const float4*)(xs + NTOK);
            wr0 = *(const float4*)(ws);
            wr1 = *(const float4*)(ws + 4);
            wr2 = *(const float4*)(ws + 8);
            wr3 = *(const float4*)(ws + 12);
        }

        #pragma unroll
        for (int s = 0; s < 2; s++) {
            const int cpa = 8 * s + quad;
            uint32_t ah[2][4], al[2][4];
            #pragma unroll
            for (int mt = 0; mt < 2; mt++) {
                int n = 32 * wn + 16 * mt + g;
                uint2 w0 = XS[cpa * 72 + n];
                uint2 w1 = XS[cpa * 72 + n + 8];
                uint2 w2 = XS[(cpa + 4) * 72 + n];
                uint2 w3 = XS[(cpa + 4) * 72 + n + 8];
                ah[mt][0] = w0.x; al[mt][0] = w0.y;
                ah[mt][1] = w1.x; al[mt][1] = w1.y;
                ah[mt][2] = w2.x; al[mt][2] = w2.y;
                ah[mt][3] = w3.x; al[mt][3] = w3.y;
            }
            #pragma unroll
            for (int ot = 0; ot < 4; ot++) {
                int o = 32 * wo + 8 * ot + g;
                uint2 b0 = WS[cpa * 136 + o];
                uint2 b1 = WS[(cpa + 4) * 136 + o];
                #pragma unroll
                for (int mt = 0; mt < 2; mt++) {
                    mma16(acc[mt][ot], al[mt], b0.x, b1.x);
                    mma16(acc[mt][ot], ah[mt], b0.y, b1.y);
                    mma16(acc[mt][ot], ah[mt], b0.x, b1.x);
                }
            }
        }
    }

    #pragma unroll
    for (int mt = 0; mt < 2; mt++)
        #pragma unroll
        for (int ot = 0; ot < 4; ot++) {
            int n = nblk + 32 * wn + 16 * mt + g;
            int o = oblk + 32 * wo + 8 * ot + 2 * quad;
            Yb[(long)o * NTOK + n]           = acc[mt][ot][0];
            Yb[(long)(o + 1) * NTOK + n]     = acc[mt][ot][1];
            Yb[(long)o * NTOK + n + 8]       = acc[mt][ot][2];
            Yb[(long)(o + 1) * NTOK + n + 8] = acc[mt][ot][3];
        }
}

// ---------------------------------------------------------------------------
// Norms: q2/k2 pre-scaled by LOG2E^2 (only attention consumes these)
// ---------------------------------------------------------------------------
__global__ void __launch_bounds__(256) norms_kernel()
{
    constexpr float L2 = 1.4426950408889634f * 1.4426950408889634f;
    int idx = blockIdx.x * 256 + threadIdx.x;
    int n = idx & (NTOK - 1);
    int t = idx >> 12;
    int h = t & 7;
    int pb = t >> 3;
    int part = pb & 1;
    int b = pb >> 1;
    const float* p = g_qkv + ((long)(b * CQKV + part * CINNER + h * DH)) * NTOK + n;
    float s = 0.f;
    #pragma unroll
    for (int d = 0; d < DH; d++) { float v = p[(long)d * NTOK]; s = fmaf(v, v, s); }
    g_norms[(long)part * (NB * NH * NTOK) + (long)(b * NH + h) * NTOK + n] = s * L2;
}

// ---------------------------------------------------------------------------
// K/V fragment pre-conversion (R9 layouts — proven conflict-behaved).
//   K word idx: nt*128 + ks*32 + lane
//   V word idx: ntp*256 + ddnt*32 + lane
// ---------------------------------------------------------------------------
__global__ void __launch_bounds__(256) frag_kernel()
{
    const int kt = blockIdx.x, bh = blockIdx.y, isV = blockIdx.z;
    const int b = bh >> 3, h = bh & 7;
    const int nk = kt * 64;
    const float* src = g_qkv + (long)(b * CQKV + (isV ? 2 : 1) * CINNER + h * DH) * NTOK;
    uint2* dst = (isV ? g_vf : g_kf) + ((long)bh * NKT + kt) * 1024;

    #pragma unroll
    for (int it = 0; it < 4; it++) {
        int w = threadIdx.x + it * 256;
        int lane = w & 31, quad = lane & 3, g = lane >> 2;
        uint2 r;
        if (!isV) {
            int nt = w >> 7, ks = (w >> 5) & 3;
            int d0 = 16 * ks + 2 * quad;
            int j = nk + 8 * nt + g;
            r.x = packh2(src[(long)d0 * NTOK + j],       src[(long)(d0 + 1) * NTOK + j]);
            r.y = packh2(src[(long)(d0 + 8) * NTOK + j], src[(long)(d0 + 9) * NTOK + j]);
        } else {
            int js = w >> 8, ddnt = (w >> 5) & 7;
            int dd = 8 * ddnt + g;
            int key0 = nk + 16 * js + 2 * quad;
            float2 v0 = *(const float2*)&src[(long)dd * NTOK + key0];
            float2 v1 = *(const float2*)&src[(long)dd * NTOK + key0 + 8];
            r.x = packh2(v0.x, v0.y);
            r.y = packh2(v1.x, v1.y);
        }
        dst[w] = r;
    }
}

// ---------------------------------------------------------------------------
// Flash distance attention: fp16 m16n8k16, pre-fragmented K/V via cp.async
// double buffering (exact R9 structure). Softmax: prescaled norms fold the
// LOG2E factors; fabs folds into MUFU operand (fmax deleted).
// ---------------------------------------------------------------------------
__global__ void __launch_bounds__(256, 2) attn_mma_kernel()
{
    __shared__ uint4 KFs[2][512];    // 2 x 8KB
    __shared__ uint4 VFs[2][512];    // 2 x 8KB
    __shared__ float k2ss[2][64];

    const int tid  = threadIdx.x;
    const int wid  = tid >> 5;
    const int lane = tid & 31;
    const int quad = lane & 3;
    const int g    = lane >> 2;
    const int n0   = blockIdx.x * 128;
    const int h = blockIdx.y, b = blockIdx.z;
    const int bh = b * NH + h;

    const float* qb  = g_qkv + (long)(b * CQKV + h * DH) * NTOK;
    const float* k2g = g_norms + (long)NB * NH * NTOK + (long)bh * NTOK;
    const uint4* kfg = (const uint4*)(g_kf + (long)bh * NKT * 1024);
    const uint4* vfg = (const uint4*)(g_vf + (long)bh * NKT * 1024);

    const uint32_t kfS = smem_u32(KFs);
    const uint32_t vfS = smem_u32(VFs);
    const uint32_t k2S = smem_u32(k2ss);

    const int i0 = n0 + wid * 16 + g;

    // Q A-fragments (fp16)
    uint32_t aq[4][4];
    #pragma unroll
    for (int ks = 0; ks < 4; ks++) {
        int d0 = 16 * ks + 2 * quad;
        aq[ks][0] = packh2(qb[(long)d0 * NTOK + i0],       qb[(long)(d0 + 1) * NTOK + i0]);
        aq[ks][1] = packh2(qb[(long)d0 * NTOK + i0 + 8],   qb[(long)(d0 + 1) * NTOK + i0 + 8]);
        aq[ks][2] = packh2(qb[(long)(d0 + 8) * NTOK + i0], qb[(long)(d0 + 9) * NTOK + i0]);
        aq[ks][3] = packh2(qb[(long)(d0 + 8) * NTOK + i0 + 8],
                           qb[(long)(d0 + 9) * NTOK + i0 + 8]);
    }
    const float q2a = g_norms[(long)bh * NTOK + i0];        // pre-scaled by LOG2E^2
    const float q2b = g_norms[(long)bh * NTOK + i0 + 8];    // pre-scaled by LOG2E^2

    constexpr float LOG2E  = 1.4426950408889634f;
    constexpr float NSHIFT = -12.0f * LOG2E;
    constexpr float M2L    = -2.0f * LOG2E * LOG2E;

    float o[8][4];
    #pragma unroll
    for (int nt = 0; nt < 8; nt++)
        #pragma unroll
        for (int r = 0; r < 4; r++) o[nt][r] = 0.f;
    float lsum0 = 0.f, lsum1 = 0.f;

    auto stage = [&](int kt, int buf) {
        const uint4* ks_ = kfg + (long)kt * 512;
        const uint4* vs_ = vfg + (long)kt * 512;
        uint32_t kd = kfS + (uint32_t)buf * 8192u + (uint32_t)tid * 16u;
        uint32_t vd = vfS + (uint32_t)buf * 8192u + (uint32_t)tid * 16u;
        cp16(kd,         ks_ + tid);
        cp16(kd + 4096u, ks_ + 256 + tid);
        cp16(vd,         vs_ + tid);
        cp16(vd + 4096u, vs_ + 256 + tid);
        if (tid < 16)
            cp16(k2S + (uint32_t)buf * 256u + (uint32_t)tid * 16u,
                 (const float4*)(k2g + kt * 64) + tid);
        CP_COMMIT();
    };

    stage(0, 0);

    for (int kt = 0; kt < NKT; kt++) {
        const int buf = kt & 1;
        CP_WAIT(0);
        __syncthreads();     // tile kt visible; all warps done with buf^1
        if (kt + 1 < NKT) stage(kt + 1, buf ^ 1);

        const uint2* KB = (const uint2*)KFs[buf];
        const uint2* VB = (const uint2*)VFs[buf];
        const float* k2p = k2ss[buf];

        #pragma unroll
        for (int ntp = 0; ntp < 4; ntp++) {
            float c[2][4];
            #pragma unroll
            for (int sub = 0; sub < 2; sub++) {
                int nt = 2 * ntp + sub;
                c[sub][0] = c[sub][1] = c[sub][2] = c[sub][3] = 0.f;
                const uint2* kfp = KB + nt * 128 + lane;
                #pragma unroll
                for (int ks = 0; ks < 4; ks++) {
                    uint2 bb = kfp[ks * 32];
                    mma16(c[sub], aq[ks], bb.x, bb.y);
                }
            }

            float p[2][4];
            #pragma unroll
            for (int sub = 0; sub < 2; sub++) {
                int nt = 2 * ntp + sub;
                float2 k2c = *(const float2*)&k2p[8 * nt + 2 * quad];
                float a0 = q2a + k2c.x, a1 = q2a + k2c.y;
                float b0_ = q2b + k2c.x, b1_ = q2b + k2c.y;
                float s;
                asm("sqrt.approx.f32 %0, %1;" : "=f"(s)
                    : "f"(fabsf(fmaf(M2L, c[sub][0], a0))));
                asm("ex2.approx.f32 %0, %1;" : "=f"(p[sub][0]) : "f"(s + NSHIFT));
                asm("sqrt.approx.f32 %0, %1;" : "=f"(s)
                    : "f"(fabsf(fmaf(M2L, c[sub][1], a1))));
                asm("ex2.approx.f32 %0, %1;" : "=f"(p[sub][1]) : "f"(s + NSHIFT));
                asm("sqrt.approx.f32 %0, %1;" : "=f"(s)
                    : "f"(fabsf(fmaf(M2L, c[sub][2], b0_))));
                asm("ex2.approx.f32 %0, %1;" : "=f"(p[sub][2]) : "f"(s + NSHIFT));
                asm("sqrt.approx.f32 %0, %1;" : "=f"(s)
                    : "f"(fabsf(fmaf(M2L, c[sub][3], b1_))));
                asm("ex2.approx.f32 %0, %1;" : "=f"(p[sub][3]) : "f"(s + NSHIFT));
                lsum0 += p[sub][0] + p[sub][1];
                lsum1 += p[sub][2] + p[sub][3];
            }

            uint32_t ap[4];
            ap[0] = packh2(p[0][0], p[0][1]);
            ap[1] = packh2(p[0][2], p[0][3]);
            ap[2] = packh2(p[1][0], p[1][1]);
            ap[3] = packh2(p[1][2], p[1][3]);

            const uint2* vfp = VB + ntp * 256 + lane;
            #pragma unroll
            for (int ddnt = 0; ddnt < 8; ddnt++) {
                uint2 vv = vfp[ddnt * 32];
                mma16(o[ddnt], ap, vv.x, vv.y);
            }
        }
    }

    lsum0 += __shfl_xor_sync(0xffffffffu, lsum0, 1);
    lsum0 += __shfl_xor_sync(0xffffffffu, lsum0, 2);
    lsum1 += __shfl_xor_sync(0xffffffffu, lsum1, 1);
    lsum1 += __shfl_xor_sync(0xffffffffu, lsum1, 2);
    const float inv0 = 1.f / lsum0;
    const float inv1 = 1.f / lsum1;

    float* aob = g_ao + (long)(b * CINNER + h * DH) * NTOK;
    #pragma unroll
    for (int nt = 0; nt < 8; nt++) {
        int dd = 8 * nt + 2 * quad;
        aob[(long)dd * NTOK + i0]           = o[nt][0] * inv0;
        aob[(long)(dd + 1) * NTOK + i0]     = o[nt][1] * inv0;
        aob[(long)dd * NTOK + i0 + 8]       = o[nt][2] * inv1;
        aob[(long)(dd + 1) * NTOK + i0 + 8] = o[nt][3] * inv1;
    }
}

// ---------------------------------------------------------------------------
extern "C" void kernel_launch(void* const* d_in, const int* in_sizes, int n_in,
                              void* d_out, int out_size)
{
    (void)in_sizes; (void)n_in; (void)out_size;
    const float* fmap  = (const float*)d_in[0];   // [2,256,64,64]
    const float* w_qkv = (const float*)d_in[1];   // [1536,256]
    const float* w_out = (const float*)d_in[2];   // [256,512]
    float* out = (float*)d_out;                   // [2,256,64,64]

    void* qkvPtr = nullptr;
    void* aoPtr  = nullptr;
    cudaGetSymbolAddress(&qkvPtr, g_qkv);
    cudaGetSymbolAddress(&aoPtr,  g_ao);

    const int gemmSmem = (16 * 72 + 16 * 136) * 8;   // 26624 B
    cudaFuncSetAttribute(gemm_tc_kernel,
                         cudaFuncAttributeMaxDynamicSharedMemorySize, gemmSmem);

    // K1: QKV projection (3xfp16 hi/lo)
    {
        dim3 grid(NTOK / 64, CQKV / 128, NB);
        gemm_tc_kernel<<<grid, 256, gemmSmem>>>(w_qkv, fmap, (float*)qkvPtr,
                                                CIN, (long)CIN * NTOK, (long)CQKV * NTOK);
    }
    // K2: norms (pre-scaled by LOG2E^2)
    norms_kernel<<<(NB * NH * 2 * NTOK) / 256, 256>>>();

    // K2.5: K/V fragment pre-conversion
    {
        dim3 grid(NKT, NB * NH, 2);
        frag_kernel<<<grid, 256>>>();
    }
    // K3: fp16 attention with cp.async fragments
    {
        dim3 grid(NTOK / 128, NH, NB);
        attn_mma_kernel<<<grid, 256>>>();
    }
    // K4: output projection (3xfp16 hi/lo)
    {
        dim3 grid(NTOK / 64, CIN / 128, NB);
        gemm_tc_kernel<<<grid, 256, gemmSmem>>>(w_out, (const float*)aoPtr, out,
                                                CINNER, (long)CINNER * NTOK, (long)CIN * NTOK);
    }
}

// round 15
// speedup vs baseline: 1.5291x; 1.0620x over previous
#include <cuda_runtime.h>
#include <cuda_fp16.h>
#include <cstdint>

// Problem constants
#define NB     2
#define CIN    256
#define NTOK   4096
#define NH     8
#define DH     64
#define CINNER 512         // NH*DH
#define CQKV   1536        // 3*CINNER
#define NKT    (NTOK / 64) // 64 key tiles

// Scratch (allocation-free rule: __device__ globals)
__device__ float g_qkv[NB * CQKV * NTOK];            // [B][1536][N]
__device__ float g_norms[2 * NB * NH * NTOK];        // q2 then k2
__device__ float g_ao[NB * CINNER * NTOK];           // attention output [B][512][N]
__device__ uint2 g_xf[NB * (CIN / 2) * NTOK];        // fmap split:  [b][cp][n]
__device__ uint2 g_wqkvf[(CIN / 2) * CQKV];          // w_qkv split: [cp][o]
// fp16 fragment-ordered K/V (R9 layout): [bh][kt][1024] uint2
//   K word idx: nt*128 + ks*32 + lane
//   V word idx: ntp*256 + ddnt*32 + lane
__device__ uint2 g_kf[NB * NH * NKT * 1024];
__device__ uint2 g_vf[NB * NH * NKT * 1024];

// ---------------------------------------------------------------------------
// helpers
// ---------------------------------------------------------------------------
__device__ __forceinline__ void mma16(float c[4], const uint32_t a[4],
                                      uint32_t b0, uint32_t b1) {
    asm volatile(
        "mma.sync.aligned.m16n8k16.row.col.f32.f16.f16.f32 "
        "{%0,%1,%2,%3}, {%4,%5,%6,%7}, {%8,%9}, {%0,%1,%2,%3};"
        : "+f"(c[0]), "+f"(c[1]), "+f"(c[2]), "+f"(c[3])
        : "r"(a[0]), "r"(a[1]), "r"(a[2]), "r"(a[3]), "r"(b0), "r"(b1));
}

__device__ __forceinline__ uint32_t packh2(float lo, float hi) {
    __half2 h = __floats2half2_rn(lo, hi);   // .x = lo (low 16 bits)
    return *(uint32_t*)&h;
}

__device__ __forceinline__ uint2 split2(float e0, float e1) {
    __half h0 = __float2half_rn(e0);
    __half h1 = __float2half_rn(e1);
    float l0 = e0 - __half2float(h0);
    float l1 = e1 - __half2float(h1);
    __half2 hh = __halves2half2(h0, h1);
    __half2 ll = __floats2half2_rn(l0, l1);
    return make_uint2(*(uint32_t*)&hh, *(uint32_t*)&ll);
}

__device__ __forceinline__ uint32_t smem_u32(const void* p) {
    uint32_t a;
    asm("{ .reg .u64 t; cvta.to.shared.u64 t, %1; cvt.u32.u64 %0, t; }"
        : "=r"(a) : "l"(p));
    return a;
}

__device__ __forceinline__ void cp16(uint32_t dst, const void* src) {
    asm volatile("cp.async.cg.shared.global [%0], [%1], 16;"
                 :: "r"(dst), "l"(src) : "memory");
}
#define CP_COMMIT() asm volatile("cp.async.commit_group;" ::: "memory")
#define CP_WAIT(n)  asm volatile("cp.async.wait_group %0;" :: "n"(n) : "memory")

// ---------------------------------------------------------------------------
// Pre-split kernels (fp32 -> fp16 {hi2,lo2} uint2 layouts) — for K1 only
// ---------------------------------------------------------------------------
__global__ void __launch_bounds__(256) xsplit_kernel(const float* __restrict__ X)
{
    long idx = (long)blockIdx.x * 256 + threadIdx.x;   // [b][cp(128)][n(4096)]
    int n = (int)(idx & 4095);
    int cp = (int)((idx >> 12) & 127);
    int b = (int)(idx >> 19);
    const float* src = X + ((long)b * CIN + 2 * cp) * NTOK + n;
    g_xf[idx] = split2(src[0], src[NTOK]);
}

__global__ void __launch_bounds__(256) wsplit_kernel(
    uint2* __restrict__ dst, const float* __restrict__ W, int M, int K)
{
    int idx = blockIdx.x * 256 + threadIdx.x;          // [cp(K/2)][o(M)]
    int cp = idx / M, o = idx - cp * M;
    dst[idx] = split2(W[(long)o * K + 2 * cp], W[(long)o * K + 2 * cp + 1]);
}

// ---------------------------------------------------------------------------
// GEMM v2 (R10, measured 80us on K1): pre-split fp16 hi/lo operands,
// cp.async double-buffered. Y^T: A=X^T, B=W. Tile 64(n) x 128(o), kTile=32.
// ---------------------------------------------------------------------------
__global__ void __launch_bounds__(256, 2) gemm_tc2_kernel(
    const uint2* __restrict__ Wf,   // [K/2][M]
    const uint2* __restrict__ Xf,   // [B][K/2][NTOK]
    float* __restrict__ Y,
    int K, int M, long xStride, long yStride)
{
    extern __shared__ uint2 sm2[];   // 2 x (1152 + 2176) uint2 = 53248 B
    const uint32_t sb = smem_u32(sm2);

    const int tid = threadIdx.x;
    const int lane = tid & 31, w = tid >> 5;
    const int quad = lane & 3, g = lane >> 2;
    const int wn = w >> 2, wo = w & 3;
    const int nblk = blockIdx.x * 64;
    const int oblk = blockIdx.y * 128;
    const uint2* Xb = Xf + (long)blockIdx.z * xStride;
    float*       Yb = Y + (long)blockIdx.z * yStride;

    float acc[2][4][4];
    #pragma unroll
    for (int mt = 0; mt < 2; mt++)
        #pragma unroll
        for (int ot = 0; ot < 4; ot++)
            #pragma unroll
            for (int r = 0; r < 4; r++) acc[mt][ot][r] = 0.f;

    auto stage = [&](int kc, int buf) {
        const int kc2 = kc >> 1;
        const uint32_t xbase = sb + (uint32_t)buf * 26624u;
        const uint32_t wbase = xbase + 9216u;
        #pragma unroll
        for (int i = 0; i < 2; i++) {          // X: 16 rows x 64 uint2
            int c = tid + i * 256;
            int row = c >> 5, wi = (c & 31) * 2;
            cp16(xbase + (uint32_t)(row * 72 + wi) * 8u,
                 Xb + (long)(kc2 + row) * NTOK + nblk + wi);
        }
        #pragma unroll
        for (int i = 0; i < 4; i++) {          // W: 16 rows x 128 uint2
            int c = tid + i * 256;
            int row = c >> 6, wi = (c & 63) * 2;
            cp16(wbase + (uint32_t)(row * 136 + wi) * 8u,
                 Wf + (long)(kc2 + row) * M + oblk + wi);
        }
        CP_COMMIT();
    };

    stage(0, 0);

    for (int kc = 0; kc < K; kc += 32) {
        const int buf = (kc >> 5) & 1;
        CP_WAIT(0);
        __syncthreads();
        if (kc + 32 < K) stage(kc + 32, buf ^ 1);

        const uint2* XS = sm2 + buf * 3328;
        const uint2* WS = XS + 1152;

        #pragma unroll
        for (int s = 0; s < 2; s++) {
            const int cpa = 8 * s + quad;
            uint32_t ah[2][4], al[2][4];
            #pragma unroll
            for (int mt = 0; mt < 2; mt++) {
                int n = 32 * wn + 16 * mt + g;
                uint2 w0 = XS[cpa * 72 + n];
                uint2 w1 = XS[cpa * 72 + n + 8];
                uint2 w2 = XS[(cpa + 4) * 72 + n];
                uint2 w3 = XS[(cpa + 4) * 72 + n + 8];
                ah[mt][0] = w0.x; al[mt][0] = w0.y;
                ah[mt][1] = w1.x; al[mt][1] = w1.y;
                ah[mt][2] = w2.x; al[mt][2] = w2.y;
                ah[mt][3] = w3.x; al[mt][3] = w3.y;
            }
            #pragma unroll
            for (int ot = 0; ot < 4; ot++) {
                int o = 32 * wo + 8 * ot + g;
                uint2 b0 = WS[cpa * 136 + o];
                uint2 b1 = WS[(cpa + 4) * 136 + o];
                #pragma unroll
                for (int mt = 0; mt < 2; mt++) {
                    mma16(acc[mt][ot], al[mt], b0.x, b1.x);
                    mma16(acc[mt][ot], ah[mt], b0.y, b1.y);
                    mma16(acc[mt][ot], ah[mt], b0.x, b1.x);
                }
            }
        }
    }

    #pragma unroll
    for (int mt = 0; mt < 2; mt++)
        #pragma unroll
        for (int ot = 0; ot < 4; ot++) {
            int n = nblk + 32 * wn + 16 * mt + g;
            int o = oblk + 32 * wo + 8 * ot + 2 * quad;
            Yb[(long)o * NTOK + n]           = acc[mt][ot][0];
            Yb[(long)(o + 1) * NTOK + n]     = acc[mt][ot][1];
            Yb[(long)o * NTOK + n + 8]       = acc[mt][ot][2];
            Yb[(long)(o + 1) * NTOK + n + 8] = acc[mt][ot][3];
        }
}

// ---------------------------------------------------------------------------
// 3xfp16 (hi/lo split) inline-staging GEMM (R9 version) — used for K4
// ---------------------------------------------------------------------------
__global__ void __launch_bounds__(256, 2) gemm_tc_kernel(
    const float* __restrict__ W, const float* __restrict__ X, float* __restrict__ Y,
    int K, long xStride, long yStride)
{
    extern __shared__ uint2 sm2[];
    uint2* XS = sm2;              // 16 x 72
    uint2* WS = sm2 + 16 * 72;    // 16 x 136

    const int tid = threadIdx.x;
    const int lane = tid & 31, w = tid >> 5;
    const int quad = lane & 3, g = lane >> 2;
    const int wn = w >> 2, wo = w & 3;
    const int nblk = blockIdx.x * 64;
    const int oblk = blockIdx.y * 128;
    const float* Xb = X + (long)blockIdx.z * xStride;
    float*       Yb = Y + (long)blockIdx.z * yStride;

    const int xrp = tid >> 4;
    const int xn4 = (tid & 15) << 2;
    const int wor = tid >> 1;
    const int wch = tid & 1;
    const float* xsrc = Xb + (long)(2 * xrp) * NTOK + nblk + xn4;
    const float* wsrc = W + (long)(oblk + wor) * K + wch * 16;

    float acc[2][4][4];
    #pragma unroll
    for (int mt = 0; mt < 2; mt++)
        #pragma unroll
        for (int ot = 0; ot < 4; ot++)
            #pragma unroll
            for (int r = 0; r < 4; r++) acc[mt][ot][r] = 0.f;

    float4 xr0 = *(const float4*)(xsrc);
    float4 xr1 = *(const float4*)(xsrc + NTOK);
    float4 wr0 = *(const float4*)(wsrc);
    float4 wr1 = *(const float4*)(wsrc + 4);
    float4 wr2 = *(const float4*)(wsrc + 8);
    float4 wr3 = *(const float4*)(wsrc + 12);

    for (int kc = 0; kc < K; kc += 32) {
        __syncthreads();
        {
            float ea[4] = {xr0.x, xr0.y, xr0.z, xr0.w};
            float eb[4] = {xr1.x, xr1.y, xr1.z, xr1.w};
            #pragma unroll
            for (int e = 0; e < 4; e++)
                XS[xrp * 72 + xn4 + e] = split2(ea[e], eb[e]);
        }
        {
            float vv[16] = {wr0.x, wr0.y, wr0.z, wr0.w, wr1.x, wr1.y, wr1.z, wr1.w,
                            wr2.x, wr2.y, wr2.z, wr2.w, wr3.x, wr3.y, wr3.z, wr3.w};
            #pragma unroll
            for (int p = 0; p < 8; p++)
                WS[(8 * wch + p) * 136 + wor] = split2(vv[2 * p], vv[2 * p + 1]);
        }
        __syncthreads();

        if (kc + 32 < K) {
            const float* xs = xsrc + (long)(kc + 32) * NTOK;
            const float* ws = wsrc + kc + 32;
            xr0 = *(const float4*)(xs);
            xr1 = *(const float4*)(xs + NTOK);
            wr0 = *(const float4*)(ws);
            wr1 = *(const float4*)(ws + 4);
            wr2 = *(const float4*)(ws + 8);
            wr3 = *(const float4*)(ws + 12);
        }

        #pragma unroll
        for (int s = 0; s < 2; s++) {
            const int cpa = 8 * s + quad;
            uint32_t ah[2][4], al[2][4];
            #pragma unroll
            for (int mt = 0; mt < 2; mt++) {
                int n = 32 * wn + 16 * mt + g;
                uint2 w0 = XS[cpa * 72 + n];
                uint2 w1 = XS[cpa * 72 + n + 8];
                uint2 w2 = XS[(cpa + 4) * 72 + n];
                uint2 w3 = XS[(cpa + 4) * 72 + n + 8];
                ah[mt][0] = w0.x; al[mt][0] = w0.y;
                ah[mt][1] = w1.x; al[mt][1] = w1.y;
                ah[mt][2] = w2.x; al[mt][2] = w2.y;
                ah[mt][3] = w3.x; al[mt][3] = w3.y;
            }
            #pragma unroll
            for (int ot = 0; ot < 4; ot++) {
                int o = 32 * wo + 8 * ot + g;
                uint2 b0 = WS[cpa * 136 + o];
                uint2 b1 = WS[(cpa + 4) * 136 + o];
                #pragma unroll
                for (int mt = 0; mt < 2; mt++) {
                    mma16(acc[mt][ot], al[mt], b0.x, b1.x);
                    mma16(acc[mt][ot], ah[mt], b0.y, b1.y);
                    mma16(acc[mt][ot], ah[mt], b0.x, b1.x);
                }
            }
        }
    }

    #pragma unroll
    for (int mt = 0; mt < 2; mt++)
        #pragma unroll
        for (int ot = 0; ot < 4; ot++) {
            int n = nblk + 32 * wn + 16 * mt + g;
            int o = oblk + 32 * wo + 8 * ot + 2 * quad;
            Yb[(long)o * NTOK + n]           = acc[mt][ot][0];
            Yb[(long)(o + 1) * NTOK + n]     = acc[mt][ot][1];
            Yb[(long)o * NTOK + n + 8]       = acc[mt][ot][2];
            Yb[(long)(o + 1) * NTOK + n + 8] = acc[mt][ot][3];
        }
}

// ---------------------------------------------------------------------------
// Norms: q2[b][h][n], k2[b][h][n]  (R9 version — unscaled)
// ---------------------------------------------------------------------------
__global__ void __launch_bounds__(256) norms_kernel()
{
    int idx = blockIdx.x * 256 + threadIdx.x;
    int n = idx & (NTOK - 1);
    int t = idx >> 12;
    int h = t & 7;
    int pb = t >> 3;
    int part = pb & 1;
    int b = pb >> 1;
    const float* p = g_qkv + ((long)(b * CQKV + part * CINNER + h * DH)) * NTOK + n;
    float s = 0.f;
    #pragma unroll
    for (int d = 0; d < DH; d++) { float v = p[(long)d * NTOK]; s = fmaf(v, v, s); }
    g_norms[(long)part * (NB * NH * NTOK) + (long)(b * NH + h) * NTOK + n] = s;
}

// ---------------------------------------------------------------------------
// K/V fragment pre-conversion (R9 layouts).
// ---------------------------------------------------------------------------
__global__ void __launch_bounds__(256) frag_kernel()
{
    const int kt = blockIdx.x, bh = blockIdx.y, isV = blockIdx.z;
    const int b = bh >> 3, h = bh & 7;
    const int nk = kt * 64;
    const float* src = g_qkv + (long)(b * CQKV + (isV ? 2 : 1) * CINNER + h * DH) * NTOK;
    uint2* dst = (isV ? g_vf : g_kf) + ((long)bh * NKT + kt) * 1024;

    #pragma unroll
    for (int it = 0; it < 4; it++) {
        int w = threadIdx.x + it * 256;
        int lane = w & 31, quad = lane & 3, g = lane >> 2;
        uint2 r;
        if (!isV) {
            int nt = w >> 7, ks = (w >> 5) & 3;
            int d0 = 16 * ks + 2 * quad;
            int j = nk + 8 * nt + g;
            r.x = packh2(src[(long)d0 * NTOK + j],       src[(long)(d0 + 1) * NTOK + j]);
            r.y = packh2(src[(long)(d0 + 8) * NTOK + j], src[(long)(d0 + 9) * NTOK + j]);
        } else {
            int js = w >> 8, ddnt = (w >> 5) & 7;
            int dd = 8 * ddnt + g;
            int key0 = nk + 16 * js + 2 * quad;
            float2 v0 = *(const float2*)&src[(long)dd * NTOK + key0];
            float2 v1 = *(const float2*)&src[(long)dd * NTOK + key0 + 8];
            r.x = packh2(v0.x, v0.y);
            r.y = packh2(v1.x, v1.y);
        }
        dst[w] = r;
    }
}

// ---------------------------------------------------------------------------
// Flash distance attention (EXACT R9 — best measured: 254us)
// ---------------------------------------------------------------------------
__global__ void __launch_bounds__(256, 2) attn_mma_kernel()
{
    __shared__ uint4 KFs[2][512];    // 2 x 8KB
    __shared__ uint4 VFs[2][512];    // 2 x 8KB
    __shared__ float k2ss[2][64];

    const int tid  = threadIdx.x;
    const int wid  = tid >> 5;
    const int lane = tid & 31;
    const int quad = lane & 3;
    const int g    = lane >> 2;
    const int n0   = blockIdx.x * 128;
    const int h = blockIdx.y, b = blockIdx.z;
    const int bh = b * NH + h;

    const float* qb  = g_qkv + (long)(b * CQKV + h * DH) * NTOK;
    const float* k2g = g_norms + (long)NB * NH * NTOK + (long)bh * NTOK;
    const uint4* kfg = (const uint4*)(g_kf + (long)bh * NKT * 1024);
    const uint4* vfg = (const uint4*)(g_vf + (long)bh * NKT * 1024);

    const uint32_t kfS = smem_u32(KFs);
    const uint32_t vfS = smem_u32(VFs);
    const uint32_t k2S = smem_u32(k2ss);

    const int i0 = n0 + wid * 16 + g;

    uint32_t aq[4][4];
    #pragma unroll
    for (int ks = 0; ks < 4; ks++) {
        int d0 = 16 * ks + 2 * quad;
        aq[ks][0] = packh2(qb[(long)d0 * NTOK + i0],       qb[(long)(d0 + 1) * NTOK + i0]);
        aq[ks][1] = packh2(qb[(long)d0 * NTOK + i0 + 8],   qb[(long)(d0 + 1) * NTOK + i0 + 8]);
        aq[ks][2] = packh2(qb[(long)(d0 + 8) * NTOK + i0], qb[(long)(d0 + 9) * NTOK + i0]);
        aq[ks][3] = packh2(qb[(long)(d0 + 8) * NTOK + i0 + 8],
                           qb[(long)(d0 + 9) * NTOK + i0 + 8]);
    }
    const float q2a = g_norms[(long)bh * NTOK + i0];
    const float q2b = g_norms[(long)bh * NTOK + i0 + 8];

    constexpr float LOG2E  = 1.4426950408889634f;
    constexpr float NSHIFT = -12.0f * LOG2E;

    float o[8][4];
    #pragma unroll
    for (int nt = 0; nt < 8; nt++)
        #pragma unroll
        for (int r = 0; r < 4; r++) o[nt][r] = 0.f;
    float lsum0 = 0.f, lsum1 = 0.f;

    auto stage = [&](int kt, int buf) {
        const uint4* ks_ = kfg + (long)kt * 512;
        const uint4* vs_ = vfg + (long)kt * 512;
        uint32_t kd = kfS + (uint32_t)buf * 8192u + (uint32_t)tid * 16u;
        uint32_t vd = vfS + (uint32_t)buf * 8192u + (uint32_t)tid * 16u;
        cp16(kd,         ks_ + tid);
        cp16(kd + 4096u, ks_ + 256 + tid);
        cp16(vd,         vs_ + tid);
        cp16(vd + 4096u, vs_ + 256 + tid);
        if (tid < 16)
            cp16(k2S + (uint32_t)buf * 256u + (uint32_t)tid * 16u,
                 (const float4*)(k2g + kt * 64) + tid);
        CP_COMMIT();
    };

    stage(0, 0);

    for (int kt = 0; kt < NKT; kt++) {
        const int buf = kt & 1;
        CP_WAIT(0);
        __syncthreads();
        if (kt + 1 < NKT) stage(kt + 1, buf ^ 1);

        const uint2* KB = (const uint2*)KFs[buf];
        const uint2* VB = (const uint2*)VFs[buf];
        const float* k2p = k2ss[buf];

        #pragma unroll
        for (int ntp = 0; ntp < 4; ntp++) {
            float c[2][4];
            #pragma unroll
            for (int sub = 0; sub < 2; sub++) {
                int nt = 2 * ntp + sub;
                c[sub][0] = c[sub][1] = c[sub][2] = c[sub][3] = 0.f;
                const uint2* kfp = KB + nt * 128 + lane;
                #pragma unroll
                for (int ks = 0; ks < 4; ks++) {
                    uint2 bb = kfp[ks * 32];
                    mma16(c[sub], aq[ks], bb.x, bb.y);
                }
            }

            float p[2][4];
            #pragma unroll
            for (int sub = 0; sub < 2; sub++) {
                int nt = 2 * ntp + sub;
                float2 k2c = *(const float2*)&k2p[8 * nt + 2 * quad];
                float a0 = q2a + k2c.x, a1 = q2a + k2c.y;
                float b0_ = q2b + k2c.x, b1_ = q2b + k2c.y;
                float d2, s;
                d2 = fmaxf(fmaf(-2.f, c[sub][0], a0), 0.f);
                asm("sqrt.approx.f32 %0, %1;" : "=f"(s) : "f"(d2));
                asm("ex2.approx.f32 %0, %1;" : "=f"(p[sub][0]) : "f"(fmaf(s, LOG2E, NSHIFT)));
                d2 = fmaxf(fmaf(-2.f, c[sub][1], a1), 0.f);
                asm("sqrt.approx.f32 %0, %1;" : "=f"(s) : "f"(d2));
                asm("ex2.approx.f32 %0, %1;" : "=f"(p[sub][1]) : "f"(fmaf(s, LOG2E, NSHIFT)));
                d2 = fmaxf(fmaf(-2.f, c[sub][2], b0_), 0.f);
                asm("sqrt.approx.f32 %0, %1;" : "=f"(s) : "f"(d2));
                asm("ex2.approx.f32 %0, %1;" : "=f"(p[sub][2]) : "f"(fmaf(s, LOG2E, NSHIFT)));
                d2 = fmaxf(fmaf(-2.f, c[sub][3], b1_), 0.f);
                asm("sqrt.approx.f32 %0, %1;" : "=f"(s) : "f"(d2));
                asm("ex2.approx.f32 %0, %1;" : "=f"(p[sub][3]) : "f"(fmaf(s, LOG2E, NSHIFT)));
                lsum0 += p[sub][0] + p[sub][1];
                lsum1 += p[sub][2] + p[sub][3];
            }

            uint32_t ap[4];
            ap[0] = packh2(p[0][0], p[0][1]);
            ap[1] = packh2(p[0][2], p[0][3]);
            ap[2] = packh2(p[1][0], p[1][1]);
            ap[3] = packh2(p[1][2], p[1][3]);

            const uint2* vfp = VB + ntp * 256 + lane;
            #pragma unroll
            for (int ddnt = 0; ddnt < 8; ddnt++) {
                uint2 vv = vfp[ddnt * 32];
                mma16(o[ddnt], ap, vv.x, vv.y);
            }
        }
    }

    lsum0 += __shfl_xor_sync(0xffffffffu, lsum0, 1);
    lsum0 += __shfl_xor_sync(0xffffffffu, lsum0, 2);
    lsum1 += __shfl_xor_sync(0xffffffffu, lsum1, 1);
    lsum1 += __shfl_xor_sync(0xffffffffu, lsum1, 2);
    const float inv0 = 1.f / lsum0;
    const float inv1 = 1.f / lsum1;

    float* aob = g_ao + (long)(b * CINNER + h * DH) * NTOK;
    #pragma unroll
    for (int nt = 0; nt < 8; nt++) {
        int dd = 8 * nt + 2 * quad;
        aob[(long)dd * NTOK + i0]           = o[nt][0] * inv0;
        aob[(long)(dd + 1) * NTOK + i0]     = o[nt][1] * inv0;
        aob[(long)dd * NTOK + i0 + 8]       = o[nt][2] * inv1;
        aob[(long)(dd + 1) * NTOK + i0 + 8] = o[nt][3] * inv1;
    }
}

// ---------------------------------------------------------------------------
extern "C" void kernel_launch(void* const* d_in, const int* in_sizes, int n_in,
                              void* d_out, int out_size)
{
    (void)in_sizes; (void)n_in; (void)out_size;
    const float* fmap  = (const float*)d_in[0];   // [2,256,64,64]
    const float* w_qkv = (const float*)d_in[1];   // [1536,256]
    const float* w_out = (const float*)d_in[2];   // [256,512]
    float* out = (float*)d_out;                   // [2,256,64,64]

    void *qkvPtr, *aoPtr, *xfPtr, *wqkvfPtr;
    cudaGetSymbolAddress(&qkvPtr,   g_qkv);
    cudaGetSymbolAddress(&aoPtr,    g_ao);
    cudaGetSymbolAddress(&xfPtr,    g_xf);
    cudaGetSymbolAddress(&wqkvfPtr, g_wqkvf);

    const int gemm2Smem = 53248;
    cudaFuncSetAttribute(gemm_tc2_kernel,
                         cudaFuncAttributeMaxDynamicSharedMemorySize, gemm2Smem);
    const int gemmSmem = (16 * 72 + 16 * 136) * 8;   // 26624 B
    cudaFuncSetAttribute(gemm_tc_kernel,
                         cudaFuncAttributeMaxDynamicSharedMemorySize, gemmSmem);

    // P0: operand pre-splits for K1
    xsplit_kernel<<<(NB * (CIN / 2) * NTOK) / 256, 256>>>(fmap);
    wsplit_kernel<<<((CIN / 2) * CQKV) / 256, 256>>>((uint2*)wqkvfPtr, w_qkv, CQKV, CIN);

    // K1: QKV projection (pre-split, cp.async — measured 80us in R10)
    {
        dim3 grid(NTOK / 64, CQKV / 128, NB);
        gemm_tc2_kernel<<<grid, 256, gemm2Smem>>>(
            (const uint2*)wqkvfPtr, (const uint2*)xfPtr, (float*)qkvPtr,
            CIN, CQKV, (long)(CIN / 2) * NTOK, (long)CQKV * NTOK);
    }
    // K2: norms
    norms_kernel<<<(NB * NH * 2 * NTOK) / 256, 256>>>();

    // K2.5: K/V fragment pre-conversion
    {
        dim3 grid(NKT, NB * NH, 2);
        frag_kernel<<<grid, 256>>>();
    }
    // K3: fp16 attention (exact R9)
    {
        dim3 grid(NTOK / 128, NH, NB);
        attn_mma_kernel<<<grid, 256>>>();
    }
    // K4: output projection (R9 inline-staging gemm)
    {
        dim3 grid(NTOK / 64, CIN / 128, NB);
        gemm_tc_kernel<<<grid, 256, gemmSmem>>>(w_out, (const float*)aoPtr, out,
                                                CINNER, (long)CINNER * NTOK, (long)CIN * NTOK);
    }
}

// round 16
// speedup vs baseline: 1.5397x; 1.0070x over previous
#include <cuda_runtime.h>
#include <cuda_fp16.h>
#include <cstdint>

// Problem constants
#define NB     2
#define CIN    256
#define NTOK   4096
#define NH     8
#define DH     64
#define CINNER 512         // NH*DH
#define CQKV   1536        // 3*CINNER
#define NKT    (NTOK / 64) // 64 key tiles

// Scratch (allocation-free rule: __device__ globals)
__device__ float g_qkv[NB * CQKV * NTOK];            // [B][1536][N]
__device__ float g_norms[2 * NB * NH * NTOK];        // q2 then k2
__device__ float g_ao[NB * CINNER * NTOK];           // attention output [B][512][N]
__device__ uint2 g_xf[NB * (CIN / 2) * NTOK];        // fmap split:  [b][cp][n]
__device__ uint2 g_aof[NB * (CINNER / 2) * NTOK];    // attn-out split
__device__ uint2 g_wqkvf[(CIN / 2) * CQKV];          // w_qkv split: [cp][o]
__device__ uint2 g_woutf[(CINNER / 2) * CIN];        // w_out split: [cp][o]
// fp16 fragment-ordered K/V (R9 layout): [bh][kt][1024] uint2
//   K word idx: nt*128 + ks*32 + lane
//   V word idx: ntp*256 + ddnt*32 + lane
__device__ uint2 g_kf[NB * NH * NKT * 1024];
__device__ uint2 g_vf[NB * NH * NKT * 1024];

// ---------------------------------------------------------------------------
// helpers
// ---------------------------------------------------------------------------
__device__ __forceinline__ void mma16(float c[4], const uint32_t a[4],
                                      uint32_t b0, uint32_t b1) {
    asm volatile(
        "mma.sync.aligned.m16n8k16.row.col.f32.f16.f16.f32 "
        "{%0,%1,%2,%3}, {%4,%5,%6,%7}, {%8,%9}, {%0,%1,%2,%3};"
        : "+f"(c[0]), "+f"(c[1]), "+f"(c[2]), "+f"(c[3])
        : "r"(a[0]), "r"(a[1]), "r"(a[2]), "r"(a[3]), "r"(b0), "r"(b1));
}

__device__ __forceinline__ uint32_t packh2(float lo, float hi) {
    __half2 h = __floats2half2_rn(lo, hi);   // .x = lo (low 16 bits)
    return *(uint32_t*)&h;
}

__device__ __forceinline__ uint2 split2(float e0, float e1) {
    __half h0 = __float2half_rn(e0);
    __half h1 = __float2half_rn(e1);
    float l0 = e0 - __half2float(h0);
    float l1 = e1 - __half2float(h1);
    __half2 hh = __halves2half2(h0, h1);
    __half2 ll = __floats2half2_rn(l0, l1);
    return make_uint2(*(uint32_t*)&hh, *(uint32_t*)&ll);
}

__device__ __forceinline__ uint32_t smem_u32(const void* p) {
    uint32_t a;
    asm("{ .reg .u64 t; cvta.to.shared.u64 t, %1; cvt.u32.u64 %0, t; }"
        : "=r"(a) : "l"(p));
    return a;
}

__device__ __forceinline__ void cp16(uint32_t dst, const void* src) {
    asm volatile("cp.async.cg.shared.global [%0], [%1], 16;"
                 :: "r"(dst), "l"(src) : "memory");
}
#define CP_COMMIT() asm volatile("cp.async.commit_group;" ::: "memory")
#define CP_WAIT(n)  asm volatile("cp.async.wait_group %0;" :: "n"(n) : "memory")

// ---------------------------------------------------------------------------
// Pre-split kernels (fp32 -> fp16 {hi2,lo2} uint2 layouts)
// ---------------------------------------------------------------------------
__global__ void __launch_bounds__(256) csplit_kernel(
    uint2* __restrict__ dst, const float* __restrict__ X, int chanPairsLog2)
{
    long idx = (long)blockIdx.x * 256 + threadIdx.x;   // [b][cp][n(4096)]
    int n = (int)(idx & 4095);
    int cp = (int)((idx >> 12) & ((1 << chanPairsLog2) - 1));
    int b = (int)(idx >> (12 + chanPairsLog2));
    const float* src = X + (((long)b << (chanPairsLog2 + 1)) + 2 * cp) * NTOK + n;
    dst[idx] = split2(src[0], src[NTOK]);
}

__global__ void __launch_bounds__(256) wsplit_kernel(
    uint2* __restrict__ dst, const float* __restrict__ W, int M, int K)
{
    int idx = blockIdx.x * 256 + threadIdx.x;          // [cp(K/2)][o(M)]
    int cp = idx / M, o = idx - cp * M;
    dst[idx] = split2(W[(long)o * K + 2 * cp], W[(long)o * K + 2 * cp + 1]);
}

// ---------------------------------------------------------------------------
// GEMM v2 (measured 80us on K1): pre-split fp16 hi/lo operands,
// cp.async double-buffered. Y^T: A=X^T, B=W. Tile 64(n) x 128(o), kTile=32.
// ---------------------------------------------------------------------------
__global__ void __launch_bounds__(256, 2) gemm_tc2_kernel(
    const uint2* __restrict__ Wf,   // [K/2][M]
    const uint2* __restrict__ Xf,   // [B][K/2][NTOK]
    float* __restrict__ Y,
    int K, int M, long xStride, long yStride)
{
    extern __shared__ uint2 sm2[];   // 2 x (1152 + 2176) uint2 = 53248 B
    const uint32_t sb = smem_u32(sm2);

    const int tid = threadIdx.x;
    const int lane = tid & 31, w = tid >> 5;
    const int quad = lane & 3, g = lane >> 2;
    const int wn = w >> 2, wo = w & 3;
    const int nblk = blockIdx.x * 64;
    const int oblk = blockIdx.y * 128;
    const uint2* Xb = Xf + (long)blockIdx.z * xStride;
    float*       Yb = Y + (long)blockIdx.z * yStride;

    float acc[2][4][4];
    #pragma unroll
    for (int mt = 0; mt < 2; mt++)
        #pragma unroll
        for (int ot = 0; ot < 4; ot++)
            #pragma unroll
            for (int r = 0; r < 4; r++) acc[mt][ot][r] = 0.f;

    auto stage = [&](int kc, int buf) {
        const int kc2 = kc >> 1;
        const uint32_t xbase = sb + (uint32_t)buf * 26624u;
        const uint32_t wbase = xbase + 9216u;
        #pragma unroll
        for (int i = 0; i < 2; i++) {          // X: 16 rows x 64 uint2
            int c = tid + i * 256;
            int row = c >> 5, wi = (c & 31) * 2;
            cp16(xbase + (uint32_t)(row * 72 + wi) * 8u,
                 Xb + (long)(kc2 + row) * NTOK + nblk + wi);
        }
        #pragma unroll
        for (int i = 0; i < 4; i++) {          // W: 16 rows x 128 uint2
            int c = tid + i * 256;
            int row = c >> 6, wi = (c & 63) * 2;
            cp16(wbase + (uint32_t)(row * 136 + wi) * 8u,
                 Wf + (long)(kc2 + row) * M + oblk + wi);
        }
        CP_COMMIT();
    };

    stage(0, 0);

    for (int kc = 0; kc < K; kc += 32) {
        const int buf = (kc >> 5) & 1;
        CP_WAIT(0);
        __syncthreads();
        if (kc + 32 < K) stage(kc + 32, buf ^ 1);

        const uint2* XS = sm2 + buf * 3328;
        const uint2* WS = XS + 1152;

        #pragma unroll
        for (int s = 0; s < 2; s++) {
            const int cpa = 8 * s + quad;
            uint32_t ah[2][4], al[2][4];
            #pragma unroll
            for (int mt = 0; mt < 2; mt++) {
                int n = 32 * wn + 16 * mt + g;
                uint2 w0 = XS[cpa * 72 + n];
                uint2 w1 = XS[cpa * 72 + n + 8];
                uint2 w2 = XS[(cpa + 4) * 72 + n];
                uint2 w3 = XS[(cpa + 4) * 72 + n + 8];
                ah[mt][0] = w0.x; al[mt][0] = w0.y;
                ah[mt][1] = w1.x; al[mt][1] = w1.y;
                ah[mt][2] = w2.x; al[mt][2] = w2.y;
                ah[mt][3] = w3.x; al[mt][3] = w3.y;
            }
            #pragma unroll
            for (int ot = 0; ot < 4; ot++) {
                int o = 32 * wo + 8 * ot + g;
                uint2 b0 = WS[cpa * 136 + o];
                uint2 b1 = WS[(cpa + 4) * 136 + o];
                #pragma unroll
                for (int mt = 0; mt < 2; mt++) {
                    mma16(acc[mt][ot], al[mt], b0.x, b1.x);
                    mma16(acc[mt][ot], ah[mt], b0.y, b1.y);
                    mma16(acc[mt][ot], ah[mt], b0.x, b1.x);
                }
            }
        }
    }

    #pragma unroll
    for (int mt = 0; mt < 2; mt++)
        #pragma unroll
        for (int ot = 0; ot < 4; ot++) {
            int n = nblk + 32 * wn + 16 * mt + g;
            int o = oblk + 32 * wo + 8 * ot + 2 * quad;
            Yb[(long)o * NTOK + n]           = acc[mt][ot][0];
            Yb[(long)(o + 1) * NTOK + n]     = acc[mt][ot][1];
            Yb[(long)o * NTOK + n + 8]       = acc[mt][ot][2];
            Yb[(long)(o + 1) * NTOK + n + 8] = acc[mt][ot][3];
        }
}

// ---------------------------------------------------------------------------
// Norms: q2[b][h][n], k2[b][h][n]
// ---------------------------------------------------------------------------
__global__ void __launch_bounds__(256) norms_kernel()
{
    int idx = blockIdx.x * 256 + threadIdx.x;
    int n = idx & (NTOK - 1);
    int t = idx >> 12;
    int h = t & 7;
    int pb = t >> 3;
    int part = pb & 1;
    int b = pb >> 1;
    const float* p = g_qkv + ((long)(b * CQKV + part * CINNER + h * DH)) * NTOK + n;
    float s = 0.f;
    #pragma unroll
    for (int d = 0; d < DH; d++) { float v = p[(long)d * NTOK]; s = fmaf(v, v, s); }
    g_norms[(long)part * (NB * NH * NTOK) + (long)(b * NH + h) * NTOK + n] = s;
}

// ---------------------------------------------------------------------------
// K/V fragment pre-conversion (R9 layouts).
// ---------------------------------------------------------------------------
__global__ void __launch_bounds__(256) frag_kernel()
{
    const int kt = blockIdx.x, bh = blockIdx.y, isV = blockIdx.z;
    const int b = bh >> 3, h = bh & 7;
    const int nk = kt * 64;
    const float* src = g_qkv + (long)(b * CQKV + (isV ? 2 : 1) * CINNER + h * DH) * NTOK;
    uint2* dst = (isV ? g_vf : g_kf) + ((long)bh * NKT + kt) * 1024;

    #pragma unroll
    for (int it = 0; it < 4; it++) {
        int w = threadIdx.x + it * 256;
        int lane = w & 31, quad = lane & 3, g = lane >> 2;
        uint2 r;
        if (!isV) {
            int nt = w >> 7, ks = (w >> 5) & 3;
            int d0 = 16 * ks + 2 * quad;
            int j = nk + 8 * nt + g;
            r.x = packh2(src[(long)d0 * NTOK + j],       src[(long)(d0 + 1) * NTOK + j]);
            r.y = packh2(src[(long)(d0 + 8) * NTOK + j], src[(long)(d0 + 9) * NTOK + j]);
        } else {
            int js = w >> 8, ddnt = (w >> 5) & 7;
            int dd = 8 * ddnt + g;
            int key0 = nk + 16 * js + 2 * quad;
            float2 v0 = *(const float2*)&src[(long)dd * NTOK + key0];
            float2 v1 = *(const float2*)&src[(long)dd * NTOK + key0 + 8];
            r.x = packh2(v0.x, v0.y);
            r.y = packh2(v1.x, v1.y);
        }
        dst[w] = r;
    }
}

// ---------------------------------------------------------------------------
// Flash distance attention (EXACT R9 — best measured: 254us)
// ---------------------------------------------------------------------------
__global__ void __launch_bounds__(256, 2) attn_mma_kernel()
{
    __shared__ uint4 KFs[2][512];    // 2 x 8KB
    __shared__ uint4 VFs[2][512];    // 2 x 8KB
    __shared__ float k2ss[2][64];

    const int tid  = threadIdx.x;
    const int wid  = tid >> 5;
    const int lane = tid & 31;
    const int quad = lane & 3;
    const int g    = lane >> 2;
    const int n0   = blockIdx.x * 128;
    const int h = blockIdx.y, b = blockIdx.z;
    const int bh = b * NH + h;

    const float* qb  = g_qkv + (long)(b * CQKV + h * DH) * NTOK;
    const float* k2g = g_norms + (long)NB * NH * NTOK + (long)bh * NTOK;
    const uint4* kfg = (const uint4*)(g_kf + (long)bh * NKT * 1024);
    const uint4* vfg = (const uint4*)(g_vf + (long)bh * NKT * 1024);

    const uint32_t kfS = smem_u32(KFs);
    const uint32_t vfS = smem_u32(VFs);
    const uint32_t k2S = smem_u32(k2ss);

    const int i0 = n0 + wid * 16 + g;

    uint32_t aq[4][4];
    #pragma unroll
    for (int ks = 0; ks < 4; ks++) {
        int d0 = 16 * ks + 2 * quad;
        aq[ks][0] = packh2(qb[(long)d0 * NTOK + i0],       qb[(long)(d0 + 1) * NTOK + i0]);
        aq[ks][1] = packh2(qb[(long)d0 * NTOK + i0 + 8],   qb[(long)(d0 + 1) * NTOK + i0 + 8]);
        aq[ks][2] = packh2(qb[(long)(d0 + 8) * NTOK + i0], qb[(long)(d0 + 9) * NTOK + i0]);
        aq[ks][3] = packh2(qb[(long)(d0 + 8) * NTOK + i0 + 8],
                           qb[(long)(d0 + 9) * NTOK + i0 + 8]);
    }
    const float q2a = g_norms[(long)bh * NTOK + i0];
    const float q2b = g_norms[(long)bh * NTOK + i0 + 8];

    constexpr float LOG2E  = 1.4426950408889634f;
    constexpr float NSHIFT = -12.0f * LOG2E;

    float o[8][4];
    #pragma unroll
    for (int nt = 0; nt < 8; nt++)
        #pragma unroll
        for (int r = 0; r < 4; r++) o[nt][r] = 0.f;
    float lsum0 = 0.f, lsum1 = 0.f;

    auto stage = [&](int kt, int buf) {
        const uint4* ks_ = kfg + (long)kt * 512;
        const uint4* vs_ = vfg + (long)kt * 512;
        uint32_t kd = kfS + (uint32_t)buf * 8192u + (uint32_t)tid * 16u;
        uint32_t vd = vfS + (uint32_t)buf * 8192u + (uint32_t)tid * 16u;
        cp16(kd,         ks_ + tid);
        cp16(kd + 4096u, ks_ + 256 + tid);
        cp16(vd,         vs_ + tid);
        cp16(vd + 4096u, vs_ + 256 + tid);
        if (tid < 16)
            cp16(k2S + (uint32_t)buf * 256u + (uint32_t)tid * 16u,
                 (const float4*)(k2g + kt * 64) + tid);
        CP_COMMIT();
    };

    stage(0, 0);

    for (int kt = 0; kt < NKT; kt++) {
        const int buf = kt & 1;
        CP_WAIT(0);
        __syncthreads();
        if (kt + 1 < NKT) stage(kt + 1, buf ^ 1);

        const uint2* KB = (const uint2*)KFs[buf];
        const uint2* VB = (const uint2*)VFs[buf];
        const float* k2p = k2ss[buf];

        #pragma unroll
        for (int ntp = 0; ntp < 4; ntp++) {
            float c[2][4];
            #pragma unroll
            for (int sub = 0; sub < 2; sub++) {
                int nt = 2 * ntp + sub;
                c[sub][0] = c[sub][1] = c[sub][2] = c[sub][3] = 0.f;
                const uint2* kfp = KB + nt * 128 + lane;
                #pragma unroll
                for (int ks = 0; ks < 4; ks++) {
                    uint2 bb = kfp[ks * 32];
                    mma16(c[sub], aq[ks], bb.x, bb.y);
                }
            }

            float p[2][4];
            #pragma unroll
            for (int sub = 0; sub < 2; sub++) {
                int nt = 2 * ntp + sub;
                float2 k2c = *(const float2*)&k2p[8 * nt + 2 * quad];
                float a0 = q2a + k2c.x, a1 = q2a + k2c.y;
                float b0_ = q2b + k2c.x, b1_ = q2b + k2c.y;
                float d2, s;
                d2 = fmaxf(fmaf(-2.f, c[sub][0], a0), 0.f);
                asm("sqrt.approx.f32 %0, %1;" : "=f"(s) : "f"(d2));
                asm("ex2.approx.f32 %0, %1;" : "=f"(p[sub][0]) : "f"(fmaf(s, LOG2E, NSHIFT)));
                d2 = fmaxf(fmaf(-2.f, c[sub][1], a1), 0.f);
                asm("sqrt.approx.f32 %0, %1;" : "=f"(s) : "f"(d2));
                asm("ex2.approx.f32 %0, %1;" : "=f"(p[sub][1]) : "f"(fmaf(s, LOG2E, NSHIFT)));
                d2 = fmaxf(fmaf(-2.f, c[sub][2], b0_), 0.f);
                asm("sqrt.approx.f32 %0, %1;" : "=f"(s) : "f"(d2));
                asm("ex2.approx.f32 %0, %1;" : "=f"(p[sub][2]) : "f"(fmaf(s, LOG2E, NSHIFT)));
                d2 = fmaxf(fmaf(-2.f, c[sub][3], b1_), 0.f);
                asm("sqrt.approx.f32 %0, %1;" : "=f"(s) : "f"(d2));
                asm("ex2.approx.f32 %0, %1;" : "=f"(p[sub][3]) : "f"(fmaf(s, LOG2E, NSHIFT)));
                lsum0 += p[sub][0] + p[sub][1];
                lsum1 += p[sub][2] + p[sub][3];
            }

            uint32_t ap[4];
            ap[0] = packh2(p[0][0], p[0][1]);
            ap[1] = packh2(p[0][2], p[0][3]);
            ap[2] = packh2(p[1][0], p[1][1]);
            ap[3] = packh2(p[1][2], p[1][3]);

            const uint2* vfp = VB + ntp * 256 + lane;
            #pragma unroll
            for (int ddnt = 0; ddnt < 8; ddnt++) {
                uint2 vv = vfp[ddnt * 32];
                mma16(o[ddnt], ap, vv.x, vv.y);
            }
        }
    }

    lsum0 += __shfl_xor_sync(0xffffffffu, lsum0, 1);
    lsum0 += __shfl_xor_sync(0xffffffffu, lsum0, 2);
    lsum1 += __shfl_xor_sync(0xffffffffu, lsum1, 1);
    lsum1 += __shfl_xor_sync(0xffffffffu, lsum1, 2);
    const float inv0 = 1.f / lsum0;
    const float inv1 = 1.f / lsum1;

    float* aob = g_ao + (long)(b * CINNER + h * DH) * NTOK;
    #pragma unroll
    for (int nt = 0; nt < 8; nt++) {
        int dd = 8 * nt + 2 * quad;
        aob[(long)dd * NTOK + i0]           = o[nt][0] * inv0;
        aob[(long)(dd + 1) * NTOK + i0]     = o[nt][1] * inv0;
        aob[(long)dd * NTOK + i0 + 8]       = o[nt][2] * inv1;
        aob[(long)(dd + 1) * NTOK + i0 + 8] = o[nt][3] * inv1;
    }
}

// ---------------------------------------------------------------------------
extern "C" void kernel_launch(void* const* d_in, const int* in_sizes, int n_in,
                              void* d_out, int out_size)
{
    (void)in_sizes; (void)n_in; (void)out_size;
    const float* fmap  = (const float*)d_in[0];   // [2,256,64,64]
    const float* w_qkv = (const float*)d_in[1];   // [1536,256]
    const float* w_out = (const float*)d_in[2];   // [256,512]
    float* out = (float*)d_out;                   // [2,256,64,64]

    void *qkvPtr, *aoPtr, *xfPtr, *aofPtr, *wqkvfPtr, *woutfPtr;
    cudaGetSymbolAddress(&qkvPtr,   g_qkv);
    cudaGetSymbolAddress(&aoPtr,    g_ao);
    cudaGetSymbolAddress(&xfPtr,    g_xf);
    cudaGetSymbolAddress(&aofPtr,   g_aof);
    cudaGetSymbolAddress(&wqkvfPtr, g_wqkvf);
    cudaGetSymbolAddress(&woutfPtr, g_woutf);

    const int gemm2Smem = 53248;
    cudaFuncSetAttribute(gemm_tc2_kernel,
                         cudaFuncAttributeMaxDynamicSharedMemorySize, gemm2Smem);

    // P0: operand pre-splits
    csplit_kernel<<<(NB * (CIN / 2) * NTOK) / 256, 256>>>(
        (uint2*)xfPtr, fmap, 7);                              // CIN/2 = 128 = 2^7
    wsplit_kernel<<<((CIN / 2) * CQKV) / 256, 256>>>((uint2*)wqkvfPtr, w_qkv, CQKV, CIN);
    wsplit_kernel<<<((CINNER / 2) * CIN) / 256, 256>>>((uint2*)woutfPtr, w_out, CIN, CINNER);

    // K1: QKV projection (pre-split, cp.async — measured 80us)
    {
        dim3 grid(NTOK / 64, CQKV / 128, NB);
        gemm_tc2_kernel<<<grid, 256, gemm2Smem>>>(
            (const uint2*)wqkvfPtr, (const uint2*)xfPtr, (float*)qkvPtr,
            CIN, CQKV, (long)(CIN / 2) * NTOK, (long)CQKV * NTOK);
    }
    // K2: norms
    norms_kernel<<<(NB * NH * 2 * NTOK) / 256, 256>>>();

    // K2.5: K/V fragment pre-conversion
    {
        dim3 grid(NKT, NB * NH, 2);
        frag_kernel<<<grid, 256>>>();
    }
    // K3: fp16 attention (exact R9)
    {
        dim3 grid(NTOK / 128, NH, NB);
        attn_mma_kernel<<<grid, 256>>>();
    }
    // P1: split attention output for K4
    csplit_kernel<<<(NB * (CINNER / 2) * NTOK) / 256, 256>>>(
        (uint2*)aofPtr, (const float*)aoPtr, 8);              // CINNER/2 = 256 = 2^8

    // K4: output projection (pre-split, cp.async)
    {
        dim3 grid(NTOK / 64, CIN / 128, NB);
        gemm_tc2_kernel<<<grid, 256, gemm2Smem>>>(
            (const uint2*)woutfPtr, (const uint2*)aofPtr, out,
            CINNER, CIN, (long)(CINNER / 2) * NTOK, (long)CIN * NTOK);
    }
}